// round 7
// baseline (speedup 1.0000x reference)
#include <cuda_runtime.h>
#include <cuda_bf16.h>
#include <cstdint>

// Problem constants (fixed by the dataset)
#define BB   4
#define LQN  4096
#define LVN  4096
#define CC   384
#define NHH  6
#define NPP  4
#define DHH  64
#define HLV  64
#define WLV  64
#define NROWS (BB*LQN)          // 16384
#define EPSF 1e-6f

// Big-GEMM tiling
#define BM 128
#define BN 128
#define BKK 64
#define NKI (CC/BKK)            // 6
#define AS_STRIDE 72            // 64 + 8 pad (bf16 elems)
#define BS_STRIDE 136           // 128 + 8 pad

// Params-GEMM tiling
#define PBM 64
#define PBN 80                  // 72 used + 8 zero-pad
#define PW_STRIDE 88            // 80 + 8 pad

// Scratch (device globals; no allocations allowed)
__device__ __nv_bfloat16 g_fnorm  [NROWS*CC];
__device__ __nv_bfloat16 g_qnorm  [NROWS*CC];
__device__ __nv_bfloat16 g_value  [NROWS*CC];
__device__ __nv_bfloat16 g_sampled[NROWS*CC];
__device__ float4        g_params [NROWS*NHH*NPP];   // (px, py, attn_w, pad)
__device__ __nv_bfloat16 g_Wv_bf  [CC*CC];
__device__ __nv_bfloat16 g_Wout_bf[CC*CC];
__device__ __nv_bfloat16 g_W72    [CC*PBN];          // [384][80]: Wo|Wa|0

// ---------------------------------------------------------------------------
// PTX helpers
// ---------------------------------------------------------------------------
__device__ __forceinline__ void ldm_x4(uint32_t &r0, uint32_t &r1, uint32_t &r2, uint32_t &r3, uint32_t addr)
{
    asm volatile("ldmatrix.sync.aligned.m8n8.x4.shared.b16 {%0,%1,%2,%3}, [%4];\n"
                 : "=r"(r0), "=r"(r1), "=r"(r2), "=r"(r3) : "r"(addr));
}
__device__ __forceinline__ void ldm_x4_trans(uint32_t &r0, uint32_t &r1, uint32_t &r2, uint32_t &r3, uint32_t addr)
{
    asm volatile("ldmatrix.sync.aligned.m8n8.x4.trans.shared.b16 {%0,%1,%2,%3}, [%4];\n"
                 : "=r"(r0), "=r"(r1), "=r"(r2), "=r"(r3) : "r"(addr));
}
__device__ __forceinline__ void mma_bf16(float* c, const uint32_t* a, uint32_t b0, uint32_t b1)
{
    asm volatile(
        "mma.sync.aligned.m16n8k16.row.col.f32.bf16.bf16.f32 "
        "{%0,%1,%2,%3}, {%4,%5,%6,%7}, {%8,%9}, {%0,%1,%2,%3};\n"
        : "+f"(c[0]), "+f"(c[1]), "+f"(c[2]), "+f"(c[3])
        : "r"(a[0]), "r"(a[1]), "r"(a[2]), "r"(a[3]), "r"(b0), "r"(b1));
}
__device__ __forceinline__ void cp_async16(void* smem, const void* gmem)
{
    uint32_t s = (uint32_t)__cvta_generic_to_shared(smem);
    asm volatile("cp.async.cg.shared.global [%0], [%1], 16;\n" :: "r"(s), "l"(gmem));
}
__device__ __forceinline__ void cp_commit()
{
    asm volatile("cp.async.commit_group;\n");
}
template<int N>
__device__ __forceinline__ void cp_wait()
{
    asm volatile("cp.async.wait_group %0;\n" :: "n"(N));
}

// ---------------------------------------------------------------------------
// Kernel 0: convert weights fp32 -> bf16 (Wv, Wout, packed [Wo|Wa|0])
// ---------------------------------------------------------------------------
__global__ void __launch_bounds__(256) convert_w_kernel(
    const float* __restrict__ Wv, const float* __restrict__ Wout,
    const float* __restrict__ Wo, const float* __restrict__ Wa)
{
    int i = blockIdx.x * 256 + threadIdx.x;
    if (i < CC*CC) {
        g_Wv_bf[i]   = __float2bfloat16(Wv[i]);
        g_Wout_bf[i] = __float2bfloat16(Wout[i]);
    }
    if (i < CC*PBN) {
        int r = i / PBN, c = i % PBN;
        float v = (c < 48) ? Wo[r*48 + c] : (c < 72 ? Wa[r*24 + c - 48] : 0.f);
        g_W72[i] = __float2bfloat16(v);
    }
}

// ---------------------------------------------------------------------------
// Kernel 1: LayerNorm. feat -> g_fnorm (bf16), query -> g_qnorm (bf16)
// ---------------------------------------------------------------------------
__global__ void __launch_bounds__(128) ln_kernel(
    const float* __restrict__ feat, const float* __restrict__ query,
    const float* __restrict__ fg, const float* __restrict__ fb,
    const float* __restrict__ qg, const float* __restrict__ qb)
{
    int row = blockIdx.x;
    bool isFeat = row < NROWS;
    const float* src = isFeat ? feat + (size_t)row*CC : query + (size_t)(row - NROWS)*CC;
    const float* g = isFeat ? fg : qg;
    const float* b = isFeat ? fb : qb;
    __nv_bfloat16* dst = isFeat ? g_fnorm + (size_t)row*CC
                                : g_qnorm + (size_t)(row - NROWS)*CC;

    int tid = threadIdx.x;
    float v[3];
    float s = 0.f, s2 = 0.f;
#pragma unroll
    for (int i = 0; i < 3; i++) {
        v[i] = src[tid + i*128];
        s  += v[i];
        s2 += v[i]*v[i];
    }
#pragma unroll
    for (int off = 16; off > 0; off >>= 1) {
        s  += __shfl_xor_sync(0xffffffffu, s,  off);
        s2 += __shfl_xor_sync(0xffffffffu, s2, off);
    }
    __shared__ float rs[4], rs2[4];
    int w = tid >> 5, l = tid & 31;
    if (l == 0) { rs[w] = s; rs2[w] = s2; }
    __syncthreads();
    s  = rs[0] + rs[1] + rs[2] + rs[3];
    s2 = rs2[0] + rs2[1] + rs2[2] + rs2[3];
    float mu  = s  * (1.f/CC);
    float var = s2 * (1.f/CC) - mu*mu;
    float inv = rsqrtf(var + EPSF);
#pragma unroll
    for (int i = 0; i < 3; i++) {
        int c = tid + i*128;
        dst[c] = __float2bfloat16((v[i]-mu)*inv*g[c] + b[c]);
    }
}

// ---------------------------------------------------------------------------
// Kernel 2/5: bf16 tensor-core GEMM (synchronous loads — measured-good R3).
//   C[16384,384] = A[16384,384] @ W[384,384]
//   MODE 0: out = g_value (bf16) = acc + bias
//   MODE 1: out = outF (f32)     = resid + gamma*(acc + bias)
// ---------------------------------------------------------------------------
template<int MODE>
__global__ void __launch_bounds__(256) mma_gemm_kernel(
    const __nv_bfloat16* __restrict__ A,
    const __nv_bfloat16* __restrict__ Bw,
    const float* __restrict__ bias,
    const float* __restrict__ resid,
    const float* __restrict__ gamma,
    float* __restrict__ outF)
{
    __shared__ __nv_bfloat16 As[BM*AS_STRIDE];
    __shared__ __nv_bfloat16 Bs[BKK*BS_STRIDE];

    int tid  = threadIdx.x;
    int warp = tid >> 5, lane = tid & 31;
    int wm = warp >> 1, wn = warp & 1;
    int rowBase = blockIdx.y * BM;
    int colBase = blockIdx.x * BN;

    float acc[2][8][4];
#pragma unroll
    for (int i = 0; i < 2; i++)
#pragma unroll
        for (int j = 0; j < 8; j++)
#pragma unroll
            for (int k = 0; k < 4; k++) acc[i][j][k] = 0.f;

    int a_mrow = (lane & 7) + ((lane >> 3) & 1) * 8;
    int a_kcol = (lane >> 4) * 8;
    int b_krow = (lane & 7) + ((lane >> 3) & 1) * 8;
    int b_ncol = (lane >> 4) * 8;

    for (int kb = 0; kb < CC; kb += BKK) {
#pragma unroll
        for (int i = 0; i < 4; i++) {
            int idx = tid + i*256;
            int r = idx >> 3, c = (idx & 7) * 8;
            *(uint4*)&As[r*AS_STRIDE + c] =
                *(const uint4*)(A + (size_t)(rowBase + r)*CC + kb + c);
        }
#pragma unroll
        for (int i = 0; i < 4; i++) {
            int idx = tid + i*256;
            int r = idx >> 4, c = (idx & 15) * 8;
            *(uint4*)&Bs[r*BS_STRIDE + c] =
                *(const uint4*)(Bw + (size_t)(kb + r)*CC + colBase + c);
        }
        __syncthreads();

#pragma unroll
        for (int ks = 0; ks < 4; ks++) {
            int k0 = ks * 16;
            uint32_t a[2][4];
#pragma unroll
            for (int mf = 0; mf < 2; mf++) {
                int mrow = wm*32 + mf*16 + a_mrow;
                uint32_t addr = (uint32_t)__cvta_generic_to_shared(
                    &As[mrow*AS_STRIDE + k0 + a_kcol]);
                ldm_x4(a[mf][0], a[mf][1], a[mf][2], a[mf][3], addr);
            }
#pragma unroll
            for (int nf4 = 0; nf4 < 4; nf4++) {
                int krow = k0 + b_krow;
                int ncol = wn*64 + nf4*16 + b_ncol;
                uint32_t addr = (uint32_t)__cvta_generic_to_shared(
                    &Bs[krow*BS_STRIDE + ncol]);
                uint32_t b0, b1, b2, b3;
                ldm_x4_trans(b0, b1, b2, b3, addr);
#pragma unroll
                for (int mf = 0; mf < 2; mf++) {
                    mma_bf16(acc[mf][nf4*2 + 0], a[mf], b0, b1);
                    mma_bf16(acc[mf][nf4*2 + 1], a[mf], b2, b3);
                }
            }
        }
        __syncthreads();
    }

    int lrow = lane >> 2;
    int lcol = (lane & 3) * 2;
#pragma unroll
    for (int mf = 0; mf < 2; mf++) {
#pragma unroll
        for (int nf = 0; nf < 8; nf++) {
            int col = colBase + wn*64 + nf*8 + lcol;
            float bx = bias[col], by = bias[col + 1];
#pragma unroll
            for (int half = 0; half < 2; half++) {
                int row = rowBase + wm*32 + mf*16 + lrow + half*8;
                float vx = acc[mf][nf][half*2 + 0] + bx;
                float vy = acc[mf][nf][half*2 + 1] + by;
                if (MODE == 0) {
                    __nv_bfloat162 o;
                    o.x = __float2bfloat16(vx);
                    o.y = __float2bfloat16(vy);
                    *(__nv_bfloat162*)&g_value[(size_t)row*CC + col] = o;
                } else {
                    const float2 rd = *(const float2*)&resid[(size_t)row*CC + col];
                    float2 o;
                    o.x = rd.x + gamma[col]   * vx;
                    o.y = rd.y + gamma[col+1] * vy;
                    *(float2*)&outF[(size_t)row*CC + col] = o;
                }
            }
        }
    }
}

// ---------------------------------------------------------------------------
// Kernel 3: params GEMM [16384x384]@[384x80] + softmax/coords, cp.async pipe.
// ---------------------------------------------------------------------------
__global__ void __launch_bounds__(128) params_mma_kernel(
    const float* __restrict__ bo, const float* __restrict__ ba,
    const float* __restrict__ refp)
{
    __shared__ __nv_bfloat16 As2[2][PBM*AS_STRIDE];    // 64 x (64+8)
    __shared__ __nv_bfloat16 Ws2[2][BKK*PW_STRIDE];    // 64 x (80+8)
    __shared__ float         S[PBM][73];

    int tid  = threadIdx.x;
    int warp = tid >> 5, lane = tid & 31;
    int rowBase = blockIdx.x * PBM;

    float acc[10][4];
#pragma unroll
    for (int j = 0; j < 10; j++)
#pragma unroll
        for (int k = 0; k < 4; k++) acc[j][k] = 0.f;

    int a_mrow = (lane & 7) + ((lane >> 3) & 1) * 8;
    int a_kcol = (lane >> 4) * 8;
    int b_krow = (lane & 7) + ((lane >> 3) & 1) * 8;
    int b_ncol = (lane >> 4) * 8;

    int a_r = tid >> 3,  a_c = (tid & 7) * 8;

    auto issue_tile = [&](int st, int kb) {
#pragma unroll
        for (int i = 0; i < 4; i++) {
            int r = a_r + i*16;
            cp_async16(&As2[st][r*AS_STRIDE + a_c],
                       g_qnorm + (size_t)(rowBase + r)*CC + kb + a_c);
        }
#pragma unroll
        for (int i = 0; i < 5; i++) {
            int idx = tid + i*128;
            int r = idx / 10, c = (idx % 10) * 8;
            cp_async16(&Ws2[st][r*PW_STRIDE + c],
                       g_W72 + (size_t)(kb + r)*PBN + c);
        }
        cp_commit();
    };

    issue_tile(0, 0);

    for (int ki = 0; ki < NKI; ki++) {
        int st = ki & 1;
        if (ki + 1 < NKI) { issue_tile(st ^ 1, (ki + 1) * BKK); cp_wait<1>(); }
        else             { cp_wait<0>(); }
        __syncthreads();

#pragma unroll
        for (int ks = 0; ks < 4; ks++) {
            int k0 = ks * 16;
            uint32_t a[4];
            {
                int mrow = warp*16 + a_mrow;
                uint32_t addr = (uint32_t)__cvta_generic_to_shared(
                    &As2[st][mrow*AS_STRIDE + k0 + a_kcol]);
                ldm_x4(a[0], a[1], a[2], a[3], addr);
            }
#pragma unroll
            for (int nf4 = 0; nf4 < 5; nf4++) {
                uint32_t addr = (uint32_t)__cvta_generic_to_shared(
                    &Ws2[st][(k0 + b_krow)*PW_STRIDE + nf4*16 + b_ncol]);
                uint32_t b0, b1, b2, b3;
                ldm_x4_trans(b0, b1, b2, b3, addr);
                mma_bf16(acc[nf4*2 + 0], a, b0, b1);
                mma_bf16(acc[nf4*2 + 1], a, b2, b3);
            }
        }
        __syncthreads();
    }

    // Stage results (cols 0..71) to shared
    int lrow = lane >> 2;
    int lcol = (lane & 3) * 2;
#pragma unroll
    for (int nf = 0; nf < 9; nf++) {
        int col = nf*8 + lcol;
#pragma unroll
        for (int half = 0; half < 2; half++) {
            int r = warp*16 + lrow + half*8;
            S[r][col]     = acc[nf][half*2 + 0];
            S[r][col + 1] = acc[nf][half*2 + 1];
        }
    }
    __syncthreads();

    // Postprocess: 64 queries x 6 heads = 384 tasks over 128 threads
#pragma unroll
    for (int i = 0; i < 3; i++) {
        int task = tid + i*128;
        int q = task / 6, h = task % 6;
        int gq = rowBase + q;
        float rx = refp[(size_t)gq*2 + 0] * (float)WLV;
        float ry = refp[(size_t)gq*2 + 1] * (float)HLV;
        float a0 = S[q][48 + h*4 + 0] + ba[h*4 + 0];
        float a1 = S[q][48 + h*4 + 1] + ba[h*4 + 1];
        float a2 = S[q][48 + h*4 + 2] + ba[h*4 + 2];
        float a3 = S[q][48 + h*4 + 3] + ba[h*4 + 3];
        float m  = fmaxf(fmaxf(a0, a1), fmaxf(a2, a3));
        float e0 = expf(a0 - m), e1 = expf(a1 - m), e2 = expf(a2 - m), e3 = expf(a3 - m);
        float inv = 1.f / (e0 + e1 + e2 + e3);
        float ws[4] = {e0*inv, e1*inv, e2*inv, e3*inv};
#pragma unroll
        for (int p = 0; p < 4; p++) {
            float px = rx + S[q][h*8 + 2*p + 0] + bo[h*8 + 2*p + 0] - 0.5f;
            float py = ry + S[q][h*8 + 2*p + 1] + bo[h*8 + 2*p + 1] - 0.5f;
            g_params[(size_t)(gq*NHH + h)*NPP + p] = make_float4(px, py, ws[p], 0.f);
        }
    }
}

// ---------------------------------------------------------------------------
// Kernel 4: bilinear sampling, weights/offsets precomputed in SMEM.
// Precompute: 48 tasks compute clamped corner offsets + validity-masked
// weights once per (query,head,point). Main phase: 16 branch-free FMA-loads
// per thread with broadcast SMEM reads.
// ---------------------------------------------------------------------------
__global__ void __launch_bounds__(384) sample_kernel()
{
    int blk = blockIdx.x;            // 8192 blocks, 2 queries each
    int tid = threadIdx.x;

    __shared__ int   s_off[2][NHH*NPP][4];
    __shared__ float s_w  [2][NHH*NPP][4];

    if (tid < 2*NHH*NPP) {
        int sub = tid / 24, i = tid % 24;
        float4 pr = g_params[(size_t)(blk*2 + sub)*24 + i];
        float x0f = floorf(pr.x), y0f = floorf(pr.y);
        float fx = pr.x - x0f, fy = pr.y - y0f;
        int ix = (int)x0f, iy = (int)y0f;
        float w00 = (1.f-fx)*(1.f-fy)*pr.z;
        float w10 = fx*(1.f-fy)*pr.z;
        float w01 = (1.f-fx)*fy*pr.z;
        float w11 = fx*fy*pr.z;
        bool xv0 = (ix   >= 0) && (ix   < WLV);
        bool xv1 = (ix+1 >= 0) && (ix+1 < WLV);
        bool yv0 = (iy   >= 0) && (iy   < HLV);
        bool yv1 = (iy+1 >= 0) && (iy+1 < HLV);
        int cx0 = min(max(ix,   0), WLV-1);
        int cx1 = min(max(ix+1, 0), WLV-1);
        int cy0 = min(max(iy,   0), HLV-1);
        int cy1 = min(max(iy+1, 0), HLV-1);
        s_w[sub][i][0] = (xv0 && yv0) ? w00 : 0.f;
        s_w[sub][i][1] = (xv1 && yv0) ? w10 : 0.f;
        s_w[sub][i][2] = (xv0 && yv1) ? w01 : 0.f;
        s_w[sub][i][3] = (xv1 && yv1) ? w11 : 0.f;
        s_off[sub][i][0] = (cy0*WLV + cx0)*CC;
        s_off[sub][i][1] = (cy0*WLV + cx1)*CC;
        s_off[sub][i][2] = (cy1*WLV + cx0)*CC;
        s_off[sub][i][3] = (cy1*WLV + cx1)*CC;
    }
    __syncthreads();

    int sub = tid / 192;
    int t   = tid % 192;
    int gq  = blk*2 + sub;
    int b   = gq >> 12;
    int h   = t >> 5;
    int dp  = t & 31;
    const __nv_bfloat16* vb = g_value + (size_t)b*LVN*CC + h*DHH + dp*2;

    float ax = 0.f, ay = 0.f;
#pragma unroll
    for (int p = 0; p < 4; p++) {
        int i = h*NPP + p;
#pragma unroll
        for (int c = 0; c < 4; c++) {
            float w   = s_w[sub][i][c];
            int   off = s_off[sub][i][c];
            float2 f = __bfloat1622float2(*(const __nv_bfloat162*)(vb + off));
            ax = fmaf(w, f.x, ax);
            ay = fmaf(w, f.y, ay);
        }
    }
    __nv_bfloat162 o;
    o.x = __float2bfloat16(ax);
    o.y = __float2bfloat16(ay);
    *(__nv_bfloat162*)&g_sampled[(size_t)gq*CC + h*DHH + dp*2] = o;
}

// ---------------------------------------------------------------------------
extern "C" void kernel_launch(void* const* d_in, const int* in_sizes, int n_in,
                              void* d_out, int out_size)
{
    const float* query = (const float*)d_in[0];
    const float* refp  = (const float*)d_in[1];
    const float* feat  = (const float*)d_in[2];
    const float* ln_q_g = (const float*)d_in[5];
    const float* ln_q_b = (const float*)d_in[6];
    const float* ln_f_g = (const float*)d_in[7];
    const float* ln_f_b = (const float*)d_in[8];
    const float* gamma  = (const float*)d_in[9];
    const float* Wv   = (const float*)d_in[10];
    const float* bv   = (const float*)d_in[11];
    const float* Wo   = (const float*)d_in[12];
    const float* bo   = (const float*)d_in[13];
    const float* Wa   = (const float*)d_in[14];
    const float* ba   = (const float*)d_in[15];
    const float* Wout = (const float*)d_in[16];
    const float* bout = (const float*)d_in[17];
    float* out = (float*)d_out;

    __nv_bfloat16 *p_fnorm, *p_sampled, *p_Wv, *p_Wout;
    cudaGetSymbolAddress((void**)&p_fnorm,   g_fnorm);
    cudaGetSymbolAddress((void**)&p_sampled, g_sampled);
    cudaGetSymbolAddress((void**)&p_Wv,      g_Wv_bf);
    cudaGetSymbolAddress((void**)&p_Wout,    g_Wout_bf);

    // 0. weights -> bf16 (incl. packed [Wo|Wa|0])
    convert_w_kernel<<<(CC*CC + 255)/256, 256>>>(Wv, Wout, Wo, Wa);

    // 1. LayerNorms (both -> bf16)
    ln_kernel<<<2*NROWS, 128>>>(feat, query, ln_f_g, ln_f_b, ln_q_g, ln_q_b);

    // 2. value = f_norm @ Wv + bv   (bf16 out)
    mma_gemm_kernel<0><<<dim3(CC/BN, NROWS/BM), 256>>>(
        p_fnorm, p_Wv, bv, nullptr, nullptr, nullptr);

    // 3. sampling params (tensor-core GEMM + softmax + coords)
    params_mma_kernel<<<NROWS/PBM, 128>>>(bo, ba, refp);

    // 4. bilinear sampling (bf16 in/out, precomputed weights)
    sample_kernel<<<NROWS/2, 384>>>();

    // 5. out = query + gamma * (sampled @ Wout + bout)
    mma_gemm_kernel<1><<<dim3(CC/BN, NROWS/BM), 256>>>(
        p_sampled, p_Wout, bout, query, gamma, out);
}

// round 8
// speedup vs baseline: 1.4622x; 1.4622x over previous
#include <cuda_runtime.h>
#include <cuda_bf16.h>
#include <cstdint>

// Problem constants (fixed by the dataset)
#define BB   4
#define LQN  4096
#define LVN  4096
#define CC   384
#define NHH  6
#define NPP  4
#define DHH  64
#define HLV  64
#define WLV  64
#define NROWS (BB*LQN)          // 16384
#define EPSF 1e-6f

// Big-GEMM tiling
#define BM 128
#define BN 128
#define BKK 64
#define NKI (CC/BKK)            // 6
#define AS_STRIDE 72            // 64 + 8 pad (bf16 elems)
#define BS_STRIDE 136           // 128 + 8 pad

// Params-GEMM tiling
#define PBM 64
#define PBN 80                  // 72 used + 8 zero-pad
#define PW_STRIDE 88            // 80 + 8 pad

// Scratch (device globals; no allocations allowed)
__device__ __nv_bfloat16 g_fnorm  [NROWS*CC];
__device__ __nv_bfloat16 g_qnorm  [NROWS*CC];
__device__ __nv_bfloat16 g_value  [NROWS*CC];
__device__ __nv_bfloat16 g_sampled[NROWS*CC];
__device__ float4        g_params [NROWS*NHH*NPP];   // (px, py, attn_w, pad)
__device__ __nv_bfloat16 g_Wv_bf  [CC*CC];
__device__ __nv_bfloat16 g_Wout_bf[CC*CC];
__device__ __nv_bfloat16 g_W72    [CC*PBN];          // [384][80]: Wo|Wa|0

// ---------------------------------------------------------------------------
// PTX helpers
// ---------------------------------------------------------------------------
__device__ __forceinline__ void ldm_x4(uint32_t &r0, uint32_t &r1, uint32_t &r2, uint32_t &r3, uint32_t addr)
{
    asm volatile("ldmatrix.sync.aligned.m8n8.x4.shared.b16 {%0,%1,%2,%3}, [%4];\n"
                 : "=r"(r0), "=r"(r1), "=r"(r2), "=r"(r3) : "r"(addr));
}
__device__ __forceinline__ void ldm_x4_trans(uint32_t &r0, uint32_t &r1, uint32_t &r2, uint32_t &r3, uint32_t addr)
{
    asm volatile("ldmatrix.sync.aligned.m8n8.x4.trans.shared.b16 {%0,%1,%2,%3}, [%4];\n"
                 : "=r"(r0), "=r"(r1), "=r"(r2), "=r"(r3) : "r"(addr));
}
__device__ __forceinline__ void mma_bf16(float* c, const uint32_t* a, uint32_t b0, uint32_t b1)
{
    asm volatile(
        "mma.sync.aligned.m16n8k16.row.col.f32.bf16.bf16.f32 "
        "{%0,%1,%2,%3}, {%4,%5,%6,%7}, {%8,%9}, {%0,%1,%2,%3};\n"
        : "+f"(c[0]), "+f"(c[1]), "+f"(c[2]), "+f"(c[3])
        : "r"(a[0]), "r"(a[1]), "r"(a[2]), "r"(a[3]), "r"(b0), "r"(b1));
}
__device__ __forceinline__ void cp_async16(void* smem, const void* gmem)
{
    uint32_t s = (uint32_t)__cvta_generic_to_shared(smem);
    asm volatile("cp.async.cg.shared.global [%0], [%1], 16;\n" :: "r"(s), "l"(gmem));
}
__device__ __forceinline__ void cp_commit()
{
    asm volatile("cp.async.commit_group;\n");
}
template<int N>
__device__ __forceinline__ void cp_wait()
{
    asm volatile("cp.async.wait_group %0;\n" :: "n"(N));
}

// ---------------------------------------------------------------------------
// Kernel 1: fused LayerNorm + weight conversion.
//   blocks [0, 2*NROWS): LN rows (feat -> g_fnorm, query -> g_qnorm, bf16)
//   blocks [2*NROWS, 2*NROWS+288): fp32 -> bf16 weight conversion + W72 pack
// ---------------------------------------------------------------------------
__global__ void __launch_bounds__(128) ln_conv_kernel(
    const float* __restrict__ feat, const float* __restrict__ query,
    const float* __restrict__ fg, const float* __restrict__ fb,
    const float* __restrict__ qg, const float* __restrict__ qb,
    const float* __restrict__ Wv, const float* __restrict__ Wout,
    const float* __restrict__ Wo, const float* __restrict__ Wa)
{
    int blk = blockIdx.x;
    int tid = threadIdx.x;

    if (blk >= 2*NROWS) {
        // weight conversion: 288 blocks x 512 elems = 147456 = CC*CC
        int base = (blk - 2*NROWS) * 512 + tid;
#pragma unroll
        for (int i = 0; i < 4; i++) {
            int idx = base + i*128;
            g_Wv_bf[idx]   = __float2bfloat16(Wv[idx]);
            g_Wout_bf[idx] = __float2bfloat16(Wout[idx]);
            if (idx < CC*PBN) {
                int r = idx / PBN, c = idx % PBN;
                float v = (c < 48) ? Wo[r*48 + c] : (c < 72 ? Wa[r*24 + c - 48] : 0.f);
                g_W72[idx] = __float2bfloat16(v);
            }
        }
        return;
    }

    bool isFeat = blk < NROWS;
    const float* src = isFeat ? feat + (size_t)blk*CC : query + (size_t)(blk - NROWS)*CC;
    const float* g = isFeat ? fg : qg;
    const float* b = isFeat ? fb : qb;
    __nv_bfloat16* dst = isFeat ? g_fnorm + (size_t)blk*CC
                                : g_qnorm + (size_t)(blk - NROWS)*CC;

    float v[3];
    float s = 0.f, s2 = 0.f;
#pragma unroll
    for (int i = 0; i < 3; i++) {
        v[i] = src[tid + i*128];
        s  += v[i];
        s2 += v[i]*v[i];
    }
#pragma unroll
    for (int off = 16; off > 0; off >>= 1) {
        s  += __shfl_xor_sync(0xffffffffu, s,  off);
        s2 += __shfl_xor_sync(0xffffffffu, s2, off);
    }
    __shared__ float rs[4], rs2[4];
    int w = tid >> 5, l = tid & 31;
    if (l == 0) { rs[w] = s; rs2[w] = s2; }
    __syncthreads();
    s  = rs[0] + rs[1] + rs[2] + rs[3];
    s2 = rs2[0] + rs2[1] + rs2[2] + rs2[3];
    float mu  = s  * (1.f/CC);
    float var = s2 * (1.f/CC) - mu*mu;
    float inv = rsqrtf(var + EPSF);
#pragma unroll
    for (int i = 0; i < 3; i++) {
        int c = tid + i*128;
        dst[c] = __float2bfloat16((v[i]-mu)*inv*g[c] + b[c]);
    }
}

// ---------------------------------------------------------------------------
// Kernel 2/5: bf16 tensor-core GEMM, 2-stage cp.async pipeline,
// __launch_bounds__(256,2) to pin regs <=128 (R4 regression = reg cliff).
//   C[16384,384] = A[16384,384] @ W[384,384]
//   MODE 0: out = g_value (bf16) = acc + bias
//   MODE 1: out = outF (f32)     = resid + gamma*(acc + bias)
// ---------------------------------------------------------------------------
template<int MODE>
__global__ void __launch_bounds__(256, 2) mma_gemm_kernel(
    const __nv_bfloat16* __restrict__ A,
    const __nv_bfloat16* __restrict__ Bw,
    const float* __restrict__ bias,
    const float* __restrict__ resid,
    const float* __restrict__ gamma,
    float* __restrict__ outF)
{
    __shared__ __nv_bfloat16 As[2][BM*AS_STRIDE];
    __shared__ __nv_bfloat16 Bs[2][BKK*BS_STRIDE];

    int tid  = threadIdx.x;
    int warp = tid >> 5, lane = tid & 31;
    int wm = warp >> 1, wn = warp & 1;
    int rowBase = blockIdx.y * BM;
    int colBase = blockIdx.x * BN;

    int a_r = tid >> 3, a_c = (tid & 7) * 8;
    int b_r = tid >> 4, b_c = (tid & 15) * 8;

    float acc[2][8][4];
#pragma unroll
    for (int i = 0; i < 2; i++)
#pragma unroll
        for (int j = 0; j < 8; j++)
#pragma unroll
            for (int k = 0; k < 4; k++) acc[i][j][k] = 0.f;

    int a_mrow = (lane & 7) + ((lane >> 3) & 1) * 8;
    int a_kcol = (lane >> 4) * 8;
    int b_krow = (lane & 7) + ((lane >> 3) & 1) * 8;
    int b_ncol = (lane >> 4) * 8;

    auto issue_tile = [&](int st, int kb) {
#pragma unroll
        for (int i = 0; i < 4; i++) {
            int r = a_r + i*32;
            cp_async16(&As[st][r*AS_STRIDE + a_c],
                       A + (size_t)(rowBase + r)*CC + kb + a_c);
        }
#pragma unroll
        for (int i = 0; i < 4; i++) {
            int r = b_r + i*16;
            cp_async16(&Bs[st][r*BS_STRIDE + b_c],
                       Bw + (size_t)(kb + r)*CC + colBase + b_c);
        }
        cp_commit();
    };

    issue_tile(0, 0);

    for (int ki = 0; ki < NKI; ki++) {
        int st = ki & 1;
        if (ki + 1 < NKI) { issue_tile(st ^ 1, (ki + 1) * BKK); cp_wait<1>(); }
        else             { cp_wait<0>(); }
        __syncthreads();

#pragma unroll
        for (int ks = 0; ks < 4; ks++) {
            int k0 = ks * 16;
            uint32_t a[2][4];
#pragma unroll
            for (int mf = 0; mf < 2; mf++) {
                int mrow = wm*32 + mf*16 + a_mrow;
                uint32_t addr = (uint32_t)__cvta_generic_to_shared(
                    &As[st][mrow*AS_STRIDE + k0 + a_kcol]);
                ldm_x4(a[mf][0], a[mf][1], a[mf][2], a[mf][3], addr);
            }
#pragma unroll
            for (int nf4 = 0; nf4 < 4; nf4++) {
                int krow = k0 + b_krow;
                int ncol = wn*64 + nf4*16 + b_ncol;
                uint32_t addr = (uint32_t)__cvta_generic_to_shared(
                    &Bs[st][krow*BS_STRIDE + ncol]);
                uint32_t b0, b1, b2, b3;
                ldm_x4_trans(b0, b1, b2, b3, addr);
#pragma unroll
                for (int mf = 0; mf < 2; mf++) {
                    mma_bf16(acc[mf][nf4*2 + 0], a[mf], b0, b1);
                    mma_bf16(acc[mf][nf4*2 + 1], a[mf], b2, b3);
                }
            }
        }
        __syncthreads();
    }

    int lrow = lane >> 2;
    int lcol = (lane & 3) * 2;
#pragma unroll
    for (int mf = 0; mf < 2; mf++) {
#pragma unroll
        for (int nf = 0; nf < 8; nf++) {
            int col = colBase + wn*64 + nf*8 + lcol;
            float bx = bias[col], by = bias[col + 1];
#pragma unroll
            for (int half = 0; half < 2; half++) {
                int row = rowBase + wm*32 + mf*16 + lrow + half*8;
                float vx = acc[mf][nf][half*2 + 0] + bx;
                float vy = acc[mf][nf][half*2 + 1] + by;
                if (MODE == 0) {
                    __nv_bfloat162 o;
                    o.x = __float2bfloat16(vx);
                    o.y = __float2bfloat16(vy);
                    *(__nv_bfloat162*)&g_value[(size_t)row*CC + col] = o;
                } else {
                    const float2 rd = *(const float2*)&resid[(size_t)row*CC + col];
                    float2 o;
                    o.x = rd.x + gamma[col]   * vx;
                    o.y = rd.y + gamma[col+1] * vy;
                    *(float2*)&outF[(size_t)row*CC + col] = o;
                }
            }
        }
    }
}

// ---------------------------------------------------------------------------
// Kernel 3: params GEMM [16384x384]@[384x80] + softmax/coords, cp.async pipe.
// UNCHANGED from R5/R7 — serves as the internal clock reference.
// ---------------------------------------------------------------------------
__global__ void __launch_bounds__(128) params_mma_kernel(
    const float* __restrict__ bo, const float* __restrict__ ba,
    const float* __restrict__ refp)
{
    __shared__ __nv_bfloat16 As2[2][PBM*AS_STRIDE];    // 64 x (64+8)
    __shared__ __nv_bfloat16 Ws2[2][BKK*PW_STRIDE];    // 64 x (80+8)
    __shared__ float         S[PBM][73];

    int tid  = threadIdx.x;
    int warp = tid >> 5, lane = tid & 31;
    int rowBase = blockIdx.x * PBM;

    float acc[10][4];
#pragma unroll
    for (int j = 0; j < 10; j++)
#pragma unroll
        for (int k = 0; k < 4; k++) acc[j][k] = 0.f;

    int a_mrow = (lane & 7) + ((lane >> 3) & 1) * 8;
    int a_kcol = (lane >> 4) * 8;
    int b_krow = (lane & 7) + ((lane >> 3) & 1) * 8;
    int b_ncol = (lane >> 4) * 8;

    int a_r = tid >> 3,  a_c = (tid & 7) * 8;

    auto issue_tile = [&](int st, int kb) {
#pragma unroll
        for (int i = 0; i < 4; i++) {
            int r = a_r + i*16;
            cp_async16(&As2[st][r*AS_STRIDE + a_c],
                       g_qnorm + (size_t)(rowBase + r)*CC + kb + a_c);
        }
#pragma unroll
        for (int i = 0; i < 5; i++) {
            int idx = tid + i*128;
            int r = idx / 10, c = (idx % 10) * 8;
            cp_async16(&Ws2[st][r*PW_STRIDE + c],
                       g_W72 + (size_t)(kb + r)*PBN + c);
        }
        cp_commit();
    };

    issue_tile(0, 0);

    for (int ki = 0; ki < NKI; ki++) {
        int st = ki & 1;
        if (ki + 1 < NKI) { issue_tile(st ^ 1, (ki + 1) * BKK); cp_wait<1>(); }
        else             { cp_wait<0>(); }
        __syncthreads();

#pragma unroll
        for (int ks = 0; ks < 4; ks++) {
            int k0 = ks * 16;
            uint32_t a[4];
            {
                int mrow = warp*16 + a_mrow;
                uint32_t addr = (uint32_t)__cvta_generic_to_shared(
                    &As2[st][mrow*AS_STRIDE + k0 + a_kcol]);
                ldm_x4(a[0], a[1], a[2], a[3], addr);
            }
#pragma unroll
            for (int nf4 = 0; nf4 < 5; nf4++) {
                uint32_t addr = (uint32_t)__cvta_generic_to_shared(
                    &Ws2[st][(k0 + b_krow)*PW_STRIDE + nf4*16 + b_ncol]);
                uint32_t b0, b1, b2, b3;
                ldm_x4_trans(b0, b1, b2, b3, addr);
                mma_bf16(acc[nf4*2 + 0], a, b0, b1);
                mma_bf16(acc[nf4*2 + 1], a, b2, b3);
            }
        }
        __syncthreads();
    }

    // Stage results (cols 0..71) to shared
    int lrow = lane >> 2;
    int lcol = (lane & 3) * 2;
#pragma unroll
    for (int nf = 0; nf < 9; nf++) {
        int col = nf*8 + lcol;
#pragma unroll
        for (int half = 0; half < 2; half++) {
            int r = warp*16 + lrow + half*8;
            S[r][col]     = acc[nf][half*2 + 0];
            S[r][col + 1] = acc[nf][half*2 + 1];
        }
    }
    __syncthreads();

    // Postprocess: 64 queries x 6 heads = 384 tasks over 128 threads
#pragma unroll
    for (int i = 0; i < 3; i++) {
        int task = tid + i*128;
        int q = task / 6, h = task % 6;
        int gq = rowBase + q;
        float rx = refp[(size_t)gq*2 + 0] * (float)WLV;
        float ry = refp[(size_t)gq*2 + 1] * (float)HLV;
        float a0 = S[q][48 + h*4 + 0] + ba[h*4 + 0];
        float a1 = S[q][48 + h*4 + 1] + ba[h*4 + 1];
        float a2 = S[q][48 + h*4 + 2] + ba[h*4 + 2];
        float a3 = S[q][48 + h*4 + 3] + ba[h*4 + 3];
        float m  = fmaxf(fmaxf(a0, a1), fmaxf(a2, a3));
        float e0 = expf(a0 - m), e1 = expf(a1 - m), e2 = expf(a2 - m), e3 = expf(a3 - m);
        float inv = 1.f / (e0 + e1 + e2 + e3);
        float ws[4] = {e0*inv, e1*inv, e2*inv, e3*inv};
#pragma unroll
        for (int p = 0; p < 4; p++) {
            float px = rx + S[q][h*8 + 2*p + 0] + bo[h*8 + 2*p + 0] - 0.5f;
            float py = ry + S[q][h*8 + 2*p + 1] + bo[h*8 + 2*p + 1] - 0.5f;
            g_params[(size_t)(gq*NHH + h)*NPP + p] = make_float4(px, py, ws[p], 0.f);
        }
    }
}

// ---------------------------------------------------------------------------
// Kernel 4: bilinear sampling, weights/offsets precomputed in SMEM.
// ---------------------------------------------------------------------------
__global__ void __launch_bounds__(384) sample_kernel()
{
    int blk = blockIdx.x;            // 8192 blocks, 2 queries each
    int tid = threadIdx.x;

    __shared__ int   s_off[2][NHH*NPP][4];
    __shared__ float s_w  [2][NHH*NPP][4];

    if (tid < 2*NHH*NPP) {
        int sub = tid / 24, i = tid % 24;
        float4 pr = g_params[(size_t)(blk*2 + sub)*24 + i];
        float x0f = floorf(pr.x), y0f = floorf(pr.y);
        float fx = pr.x - x0f, fy = pr.y - y0f;
        int ix = (int)x0f, iy = (int)y0f;
        float w00 = (1.f-fx)*(1.f-fy)*pr.z;
        float w10 = fx*(1.f-fy)*pr.z;
        float w01 = (1.f-fx)*fy*pr.z;
        float w11 = fx*fy*pr.z;
        bool xv0 = (ix   >= 0) && (ix   < WLV);
        bool xv1 = (ix+1 >= 0) && (ix+1 < WLV);
        bool yv0 = (iy   >= 0) && (iy   < HLV);
        bool yv1 = (iy+1 >= 0) && (iy+1 < HLV);
        int cx0 = min(max(ix,   0), WLV-1);
        int cx1 = min(max(ix+1, 0), WLV-1);
        int cy0 = min(max(iy,   0), HLV-1);
        int cy1 = min(max(iy+1, 0), HLV-1);
        s_w[sub][i][0] = (xv0 && yv0) ? w00 : 0.f;
        s_w[sub][i][1] = (xv1 && yv0) ? w10 : 0.f;
        s_w[sub][i][2] = (xv0 && yv1) ? w01 : 0.f;
        s_w[sub][i][3] = (xv1 && yv1) ? w11 : 0.f;
        s_off[sub][i][0] = (cy0*WLV + cx0)*CC;
        s_off[sub][i][1] = (cy0*WLV + cx1)*CC;
        s_off[sub][i][2] = (cy1*WLV + cx0)*CC;
        s_off[sub][i][3] = (cy1*WLV + cx1)*CC;
    }
    __syncthreads();

    int sub = tid / 192;
    int t   = tid % 192;
    int gq  = blk*2 + sub;
    int b   = gq >> 12;
    int h   = t >> 5;
    int dp  = t & 31;
    const __nv_bfloat16* vb = g_value + (size_t)b*LVN*CC + h*DHH + dp*2;

    float ax = 0.f, ay = 0.f;
#pragma unroll
    for (int p = 0; p < 4; p++) {
        int i = h*NPP + p;
#pragma unroll
        for (int c = 0; c < 4; c++) {
            float w   = s_w[sub][i][c];
            int   off = s_off[sub][i][c];
            float2 f = __bfloat1622float2(*(const __nv_bfloat162*)(vb + off));
            ax = fmaf(w, f.x, ax);
            ay = fmaf(w, f.y, ay);
        }
    }
    __nv_bfloat162 o;
    o.x = __float2bfloat16(ax);
    o.y = __float2bfloat16(ay);
    *(__nv_bfloat162*)&g_sampled[(size_t)gq*CC + h*DHH + dp*2] = o;
}

// ---------------------------------------------------------------------------
extern "C" void kernel_launch(void* const* d_in, const int* in_sizes, int n_in,
                              void* d_out, int out_size)
{
    const float* query = (const float*)d_in[0];
    const float* refp  = (const float*)d_in[1];
    const float* feat  = (const float*)d_in[2];
    const float* ln_q_g = (const float*)d_in[5];
    const float* ln_q_b = (const float*)d_in[6];
    const float* ln_f_g = (const float*)d_in[7];
    const float* ln_f_b = (const float*)d_in[8];
    const float* gamma  = (const float*)d_in[9];
    const float* Wv   = (const float*)d_in[10];
    const float* bv   = (const float*)d_in[11];
    const float* Wo   = (const float*)d_in[12];
    const float* bo   = (const float*)d_in[13];
    const float* Wa   = (const float*)d_in[14];
    const float* ba   = (const float*)d_in[15];
    const float* Wout = (const float*)d_in[16];
    const float* bout = (const float*)d_in[17];
    float* out = (float*)d_out;

    __nv_bfloat16 *p_fnorm, *p_sampled, *p_Wv, *p_Wout;
    cudaGetSymbolAddress((void**)&p_fnorm,   g_fnorm);
    cudaGetSymbolAddress((void**)&p_sampled, g_sampled);
    cudaGetSymbolAddress((void**)&p_Wv,      g_Wv_bf);
    cudaGetSymbolAddress((void**)&p_Wout,    g_Wout_bf);

    // 1. LayerNorms (both -> bf16) + weight conversion, fused
    ln_conv_kernel<<<2*NROWS + 288, 128>>>(
        feat, query, ln_f_g, ln_f_b, ln_q_g, ln_q_b, Wv, Wout, Wo, Wa);

    // 2. value = f_norm @ Wv + bv   (bf16 out)
    mma_gemm_kernel<0><<<dim3(CC/BN, NROWS/BM), 256>>>(
        p_fnorm, p_Wv, bv, nullptr, nullptr, nullptr);

    // 3. sampling params (tensor-core GEMM + softmax + coords)
    params_mma_kernel<<<NROWS/PBM, 128>>>(bo, ba, refp);

    // 4. bilinear sampling (bf16 in/out, precomputed weights)
    sample_kernel<<<NROWS/2, 384>>>();

    // 5. out = query + gamma * (sampled @ Wout + bout)
    mma_gemm_kernel<1><<<dim3(CC/BN, NROWS/BM), 256>>>(
        p_sampled, p_Wout, bout, query, gamma, out);
}

// round 12
// speedup vs baseline: 1.6015x; 1.0952x over previous
#include <cuda_runtime.h>
#include <cuda_bf16.h>
#include <cstdint>

// Problem constants (fixed by the dataset)
#define BB   4
#define LQN  4096
#define LVN  4096
#define CC   384
#define NHH  6
#define NPP  4
#define DHH  64
#define HLV  64
#define WLV  64
#define NROWS (BB*LQN)          // 16384
#define EPSF 1e-6f

// Big-GEMM tiling
#define BM 128
#define BN 128
#define BKK 64
#define NKI (CC/BKK)            // 6
#define AS_STRIDE 72            // 64 + 8 pad (bf16 elems)
#define BS_STRIDE 136           // 128 + 8 pad

// Params-GEMM tiling
#define PBM 64
#define PBN 80                  // 72 used + 8 zero-pad
#define PW_STRIDE 88            // 80 + 8 pad

// Scratch (device globals; no allocations allowed)
__device__ __nv_bfloat16 g_fnorm  [NROWS*CC];
__device__ __nv_bfloat16 g_qnorm  [NROWS*CC];
__device__ __nv_bfloat16 g_value  [NROWS*CC];
__device__ __nv_bfloat16 g_sampled[NROWS*CC];
__device__ float4        g_params [NROWS*NHH*NPP];   // (px, py, attn_w, pad)
__device__ __nv_bfloat16 g_Wv_bf  [CC*CC];
__device__ __nv_bfloat16 g_Wout_bf[CC*CC];
__device__ __nv_bfloat16 g_W72    [CC*PBN];          // [384][80]: Wo|Wa|0

// ---------------------------------------------------------------------------
// PTX helpers
// ---------------------------------------------------------------------------
__device__ __forceinline__ void ldm_x4(uint32_t &r0, uint32_t &r1, uint32_t &r2, uint32_t &r3, uint32_t addr)
{
    asm volatile("ldmatrix.sync.aligned.m8n8.x4.shared.b16 {%0,%1,%2,%3}, [%4];\n"
                 : "=r"(r0), "=r"(r1), "=r"(r2), "=r"(r3) : "r"(addr));
}
__device__ __forceinline__ void ldm_x4_trans(uint32_t &r0, uint32_t &r1, uint32_t &r2, uint32_t &r3, uint32_t addr)
{
    asm volatile("ldmatrix.sync.aligned.m8n8.x4.trans.shared.b16 {%0,%1,%2,%3}, [%4];\n"
                 : "=r"(r0), "=r"(r1), "=r"(r2), "=r"(r3) : "r"(addr));
}
__device__ __forceinline__ void mma_bf16(float* c, const uint32_t* a, uint32_t b0, uint32_t b1)
{
    asm volatile(
        "mma.sync.aligned.m16n8k16.row.col.f32.bf16.bf16.f32 "
        "{%0,%1,%2,%3}, {%4,%5,%6,%7}, {%8,%9}, {%0,%1,%2,%3};\n"
        : "+f"(c[0]), "+f"(c[1]), "+f"(c[2]), "+f"(c[3])
        : "r"(a[0]), "r"(a[1]), "r"(a[2]), "r"(a[3]), "r"(b0), "r"(b1));
}
__device__ __forceinline__ void cp_async16(void* smem, const void* gmem)
{
    uint32_t s = (uint32_t)__cvta_generic_to_shared(smem);
    asm volatile("cp.async.cg.shared.global [%0], [%1], 16;\n" :: "r"(s), "l"(gmem));
}
__device__ __forceinline__ void cp_commit()
{
    asm volatile("cp.async.commit_group;\n");
}
template<int N>
__device__ __forceinline__ void cp_wait()
{
    asm volatile("cp.async.wait_group %0;\n" :: "n"(N));
}

// ---------------------------------------------------------------------------
// Kernel 1: fused LayerNorm + weight conversion.
// ---------------------------------------------------------------------------
__global__ void __launch_bounds__(128) ln_conv_kernel(
    const float* __restrict__ feat, const float* __restrict__ query,
    const float* __restrict__ fg, const float* __restrict__ fb,
    const float* __restrict__ qg, const float* __restrict__ qb,
    const float* __restrict__ Wv, const float* __restrict__ Wout,
    const float* __restrict__ Wo, const float* __restrict__ Wa)
{
    int blk = blockIdx.x;
    int tid = threadIdx.x;

    if (blk >= 2*NROWS) {
        int base = (blk - 2*NROWS) * 512 + tid;
#pragma unroll
        for (int i = 0; i < 4; i++) {
            int idx = base + i*128;
            g_Wv_bf[idx]   = __float2bfloat16(Wv[idx]);
            g_Wout_bf[idx] = __float2bfloat16(Wout[idx]);
            if (idx < CC*PBN) {
                int r = idx / PBN, c = idx % PBN;
                float v = (c < 48) ? Wo[r*48 + c] : (c < 72 ? Wa[r*24 + c - 48] : 0.f);
                g_W72[idx] = __float2bfloat16(v);
            }
        }
        return;
    }

    bool isFeat = blk < NROWS;
    const float* src = isFeat ? feat + (size_t)blk*CC : query + (size_t)(blk - NROWS)*CC;
    const float* g = isFeat ? fg : qg;
    const float* b = isFeat ? fb : qb;
    __nv_bfloat16* dst = isFeat ? g_fnorm + (size_t)blk*CC
                                : g_qnorm + (size_t)(blk - NROWS)*CC;

    float v[3];
    float s = 0.f, s2 = 0.f;
#pragma unroll
    for (int i = 0; i < 3; i++) {
        v[i] = src[tid + i*128];
        s  += v[i];
        s2 += v[i]*v[i];
    }
#pragma unroll
    for (int off = 16; off > 0; off >>= 1) {
        s  += __shfl_xor_sync(0xffffffffu, s,  off);
        s2 += __shfl_xor_sync(0xffffffffu, s2, off);
    }
    __shared__ float rs[4], rs2[4];
    int w = tid >> 5, l = tid & 31;
    if (l == 0) { rs[w] = s; rs2[w] = s2; }
    __syncthreads();
    s  = rs[0] + rs[1] + rs[2] + rs[3];
    s2 = rs2[0] + rs2[1] + rs2[2] + rs2[3];
    float mu  = s  * (1.f/CC);
    float var = s2 * (1.f/CC) - mu*mu;
    float inv = rsqrtf(var + EPSF);
#pragma unroll
    for (int i = 0; i < 3; i++) {
        int c = tid + i*128;
        dst[c] = __float2bfloat16((v[i]-mu)*inv*g[c] + b[c]);
    }
}

// ---------------------------------------------------------------------------
// Kernel 2/5: bf16 tensor-core GEMM, 2-stage cp.async pipeline, 2 CTAs/SM.
// ---------------------------------------------------------------------------
template<int MODE>
__global__ void __launch_bounds__(256, 2) mma_gemm_kernel(
    const __nv_bfloat16* __restrict__ A,
    const __nv_bfloat16* __restrict__ Bw,
    const float* __restrict__ bias,
    const float* __restrict__ resid,
    const float* __restrict__ gamma,
    float* __restrict__ outF)
{
    __shared__ __nv_bfloat16 As[2][BM*AS_STRIDE];
    __shared__ __nv_bfloat16 Bs[2][BKK*BS_STRIDE];

    int tid  = threadIdx.x;
    int warp = tid >> 5, lane = tid & 31;
    int wm = warp >> 1, wn = warp & 1;
    int rowBase = blockIdx.y * BM;
    int colBase = blockIdx.x * BN;

    int a_r = tid >> 3, a_c = (tid & 7) * 8;
    int b_r = tid >> 4, b_c = (tid & 15) * 8;

    float acc[2][8][4];
#pragma unroll
    for (int i = 0; i < 2; i++)
#pragma unroll
        for (int j = 0; j < 8; j++)
#pragma unroll
            for (int k = 0; k < 4; k++) acc[i][j][k] = 0.f;

    int a_mrow = (lane & 7) + ((lane >> 3) & 1) * 8;
    int a_kcol = (lane >> 4) * 8;
    int b_krow = (lane & 7) + ((lane >> 3) & 1) * 8;
    int b_ncol = (lane >> 4) * 8;

    auto issue_tile = [&](int st, int kb) {
#pragma unroll
        for (int i = 0; i < 4; i++) {
            int r = a_r + i*32;
            cp_async16(&As[st][r*AS_STRIDE + a_c],
                       A + (size_t)(rowBase + r)*CC + kb + a_c);
        }
#pragma unroll
        for (int i = 0; i < 4; i++) {
            int r = b_r + i*16;
            cp_async16(&Bs[st][r*BS_STRIDE + b_c],
                       Bw + (size_t)(kb + r)*CC + colBase + b_c);
        }
        cp_commit();
    };

    issue_tile(0, 0);

    for (int ki = 0; ki < NKI; ki++) {
        int st = ki & 1;
        if (ki + 1 < NKI) { issue_tile(st ^ 1, (ki + 1) * BKK); cp_wait<1>(); }
        else             { cp_wait<0>(); }
        __syncthreads();

#pragma unroll
        for (int ks = 0; ks < 4; ks++) {
            int k0 = ks * 16;
            uint32_t a[2][4];
#pragma unroll
            for (int mf = 0; mf < 2; mf++) {
                int mrow = wm*32 + mf*16 + a_mrow;
                uint32_t addr = (uint32_t)__cvta_generic_to_shared(
                    &As[st][mrow*AS_STRIDE + k0 + a_kcol]);
                ldm_x4(a[mf][0], a[mf][1], a[mf][2], a[mf][3], addr);
            }
#pragma unroll
            for (int nf4 = 0; nf4 < 4; nf4++) {
                int krow = k0 + b_krow;
                int ncol = wn*64 + nf4*16 + b_ncol;
                uint32_t addr = (uint32_t)__cvta_generic_to_shared(
                    &Bs[st][krow*BS_STRIDE + ncol]);
                uint32_t b0, b1, b2, b3;
                ldm_x4_trans(b0, b1, b2, b3, addr);
#pragma unroll
                for (int mf = 0; mf < 2; mf++) {
                    mma_bf16(acc[mf][nf4*2 + 0], a[mf], b0, b1);
                    mma_bf16(acc[mf][nf4*2 + 1], a[mf], b2, b3);
                }
            }
        }
        __syncthreads();
    }

    int lrow = lane >> 2;
    int lcol = (lane & 3) * 2;
#pragma unroll
    for (int mf = 0; mf < 2; mf++) {
#pragma unroll
        for (int nf = 0; nf < 8; nf++) {
            int col = colBase + wn*64 + nf*8 + lcol;
            float bx = bias[col], by = bias[col + 1];
#pragma unroll
            for (int half = 0; half < 2; half++) {
                int row = rowBase + wm*32 + mf*16 + lrow + half*8;
                float vx = acc[mf][nf][half*2 + 0] + bx;
                float vy = acc[mf][nf][half*2 + 1] + by;
                if (MODE == 0) {
                    __nv_bfloat162 o;
                    o.x = __float2bfloat16(vx);
                    o.y = __float2bfloat16(vy);
                    *(__nv_bfloat162*)&g_value[(size_t)row*CC + col] = o;
                } else {
                    const float2 rd = *(const float2*)&resid[(size_t)row*CC + col];
                    float2 o;
                    o.x = rd.x + gamma[col]   * vx;
                    o.y = rd.y + gamma[col+1] * vy;
                    *(float2*)&outF[(size_t)row*CC + col] = o;
                }
            }
        }
    }
}

// ---------------------------------------------------------------------------
// Kernel 3: params GEMM [16384x384]@[384x80] + softmax/coords, cp.async pipe.
// UNCHANGED — internal clock reference.
// ---------------------------------------------------------------------------
__global__ void __launch_bounds__(128) params_mma_kernel(
    const float* __restrict__ bo, const float* __restrict__ ba,
    const float* __restrict__ refp)
{
    __shared__ __nv_bfloat16 As2[2][PBM*AS_STRIDE];    // 64 x (64+8)
    __shared__ __nv_bfloat16 Ws2[2][BKK*PW_STRIDE];    // 64 x (80+8)
    __shared__ float         S[PBM][73];

    int tid  = threadIdx.x;
    int warp = tid >> 5, lane = tid & 31;
    int rowBase = blockIdx.x * PBM;

    float acc[10][4];
#pragma unroll
    for (int j = 0; j < 10; j++)
#pragma unroll
        for (int k = 0; k < 4; k++) acc[j][k] = 0.f;

    int a_mrow = (lane & 7) + ((lane >> 3) & 1) * 8;
    int a_kcol = (lane >> 4) * 8;
    int b_krow = (lane & 7) + ((lane >> 3) & 1) * 8;
    int b_ncol = (lane >> 4) * 8;

    int a_r = tid >> 3,  a_c = (tid & 7) * 8;

    auto issue_tile = [&](int st, int kb) {
#pragma unroll
        for (int i = 0; i < 4; i++) {
            int r = a_r + i*16;
            cp_async16(&As2[st][r*AS_STRIDE + a_c],
                       g_qnorm + (size_t)(rowBase + r)*CC + kb + a_c);
        }
#pragma unroll
        for (int i = 0; i < 5; i++) {
            int idx = tid + i*128;
            int r = idx / 10, c = (idx % 10) * 8;
            cp_async16(&Ws2[st][r*PW_STRIDE + c],
                       g_W72 + (size_t)(kb + r)*PBN + c);
        }
        cp_commit();
    };

    issue_tile(0, 0);

    for (int ki = 0; ki < NKI; ki++) {
        int st = ki & 1;
        if (ki + 1 < NKI) { issue_tile(st ^ 1, (ki + 1) * BKK); cp_wait<1>(); }
        else             { cp_wait<0>(); }
        __syncthreads();

#pragma unroll
        for (int ks = 0; ks < 4; ks++) {
            int k0 = ks * 16;
            uint32_t a[4];
            {
                int mrow = warp*16 + a_mrow;
                uint32_t addr = (uint32_t)__cvta_generic_to_shared(
                    &As2[st][mrow*AS_STRIDE + k0 + a_kcol]);
                ldm_x4(a[0], a[1], a[2], a[3], addr);
            }
#pragma unroll
            for (int nf4 = 0; nf4 < 5; nf4++) {
                uint32_t addr = (uint32_t)__cvta_generic_to_shared(
                    &Ws2[st][(k0 + b_krow)*PW_STRIDE + nf4*16 + b_ncol]);
                uint32_t b0, b1, b2, b3;
                ldm_x4_trans(b0, b1, b2, b3, addr);
                mma_bf16(acc[nf4*2 + 0], a, b0, b1);
                mma_bf16(acc[nf4*2 + 1], a, b2, b3);
            }
        }
        __syncthreads();
    }

    int lrow = lane >> 2;
    int lcol = (lane & 3) * 2;
#pragma unroll
    for (int nf = 0; nf < 9; nf++) {
        int col = nf*8 + lcol;
#pragma unroll
        for (int half = 0; half < 2; half++) {
            int r = warp*16 + lrow + half*8;
            S[r][col]     = acc[nf][half*2 + 0];
            S[r][col + 1] = acc[nf][half*2 + 1];
        }
    }
    __syncthreads();

#pragma unroll
    for (int i = 0; i < 3; i++) {
        int task = tid + i*128;
        int q = task / 6, h = task % 6;
        int gq = rowBase + q;
        float rx = refp[(size_t)gq*2 + 0] * (float)WLV;
        float ry = refp[(size_t)gq*2 + 1] * (float)HLV;
        float a0 = S[q][48 + h*4 + 0] + ba[h*4 + 0];
        float a1 = S[q][48 + h*4 + 1] + ba[h*4 + 1];
        float a2 = S[q][48 + h*4 + 2] + ba[h*4 + 2];
        float a3 = S[q][48 + h*4 + 3] + ba[h*4 + 3];
        float m  = fmaxf(fmaxf(a0, a1), fmaxf(a2, a3));
        float e0 = expf(a0 - m), e1 = expf(a1 - m), e2 = expf(a2 - m), e3 = expf(a3 - m);
        float inv = 1.f / (e0 + e1 + e2 + e3);
        float ws[4] = {e0*inv, e1*inv, e2*inv, e3*inv};
#pragma unroll
        for (int p = 0; p < 4; p++) {
            float px = rx + S[q][h*8 + 2*p + 0] + bo[h*8 + 2*p + 0] - 0.5f;
            float py = ry + S[q][h*8 + 2*p + 1] + bo[h*8 + 2*p + 1] - 0.5f;
            g_params[(size_t)(gq*NHH + h)*NPP + p] = make_float4(px, py, ws[p], 0.f);
        }
    }
}

// ---------------------------------------------------------------------------
// Kernel 4: bilinear sampling, HFMA2 bf16 path.
// 4 queries/block (96 threads each: h = t/16, channel group dg = t%16, 4 ch).
// Precompute: 96 tasks build bf16x2-broadcast masked weights + clamped
// offsets. Main: per corner = LDS w + LDS off + IMAD + LDG.64 + 2 HFMA2,
// accumulating directly in bf16x2 (no f32 conversions at all).
// ---------------------------------------------------------------------------
__global__ void __launch_bounds__(384) sample_kernel()
{
    int blk = blockIdx.x;            // 4096 blocks, 4 queries each
    int tid = threadIdx.x;

    __shared__ uint32_t s_wb [4][NHH*NPP][4];   // bf16x2 broadcast weights
    __shared__ int      s_off[4][NHH*NPP][4];   // element offsets into value

    if (tid < 4*NHH*NPP) {
        int sub = tid / 24, i = tid % 24;
        float4 pr = g_params[(size_t)(blk*4 + sub)*24 + i];
        float x0f = floorf(pr.x), y0f = floorf(pr.y);
        float fx = pr.x - x0f, fy = pr.y - y0f;
        int ix = (int)x0f, iy = (int)y0f;
        float w00 = (1.f-fx)*(1.f-fy)*pr.z;
        float w10 = fx*(1.f-fy)*pr.z;
        float w01 = (1.f-fx)*fy*pr.z;
        float w11 = fx*fy*pr.z;
        bool xv0 = (ix   >= 0) && (ix   < WLV);
        bool xv1 = (ix+1 >= 0) && (ix+1 < WLV);
        bool yv0 = (iy   >= 0) && (iy   < HLV);
        bool yv1 = (iy+1 >= 0) && (iy+1 < HLV);
        int cx0 = min(max(ix,   0), WLV-1);
        int cx1 = min(max(ix+1, 0), WLV-1);
        int cy0 = min(max(iy,   0), HLV-1);
        int cy1 = min(max(iy+1, 0), HLV-1);
        float wf[4];
        wf[0] = (xv0 && yv0) ? w00 : 0.f;
        wf[1] = (xv1 && yv0) ? w10 : 0.f;
        wf[2] = (xv0 && yv1) ? w01 : 0.f;
        wf[3] = (xv1 && yv1) ? w11 : 0.f;
#pragma unroll
        for (int c = 0; c < 4; c++) {
            __nv_bfloat162 wb = __float2bfloat162_rn(wf[c]);
            s_wb[sub][i][c] = *(uint32_t*)&wb;
        }
        s_off[sub][i][0] = (cy0*WLV + cx0)*CC;
        s_off[sub][i][1] = (cy0*WLV + cx1)*CC;
        s_off[sub][i][2] = (cy1*WLV + cx0)*CC;
        s_off[sub][i][3] = (cy1*WLV + cx1)*CC;
    }
    __syncthreads();

    int sub = tid / 96;              // query within block
    int t   = tid % 96;
    int gq  = blk*4 + sub;
    int b   = gq >> 12;
    int h   = t >> 4;                // 0..5
    int dg  = t & 15;                // channel group (4 channels = 8 bytes)
    const __nv_bfloat16* vb = g_value + (size_t)b*LVN*CC + h*DHH + dg*4;

    __nv_bfloat162 acc01 = __float2bfloat162_rn(0.f);
    __nv_bfloat162 acc23 = __float2bfloat162_rn(0.f);
#pragma unroll
    for (int p = 0; p < 4; p++) {
        int i = h*NPP + p;
#pragma unroll
        for (int c = 0; c < 4; c++) {
            uint32_t wraw = s_wb[sub][i][c];
            int      off  = s_off[sub][i][c];
            uint2 raw = *(const uint2*)(vb + off);
            __nv_bfloat162 wb = *(__nv_bfloat162*)&wraw;
            acc01 = __hfma2(wb, *(__nv_bfloat162*)&raw.x, acc01);
            acc23 = __hfma2(wb, *(__nv_bfloat162*)&raw.y, acc23);
        }
    }
    uint2 o;
    o.x = *(uint32_t*)&acc01;
    o.y = *(uint32_t*)&acc23;
    *(uint2*)&g_sampled[(size_t)gq*CC + h*DHH + dg*4] = o;
}

// ---------------------------------------------------------------------------
extern "C" void kernel_launch(void* const* d_in, const int* in_sizes, int n_in,
                              void* d_out, int out_size)
{
    const float* query = (const float*)d_in[0];
    const float* refp  = (const float*)d_in[1];
    const float* feat  = (const float*)d_in[2];
    const float* ln_q_g = (const float*)d_in[5];
    const float* ln_q_b = (const float*)d_in[6];
    const float* ln_f_g = (const float*)d_in[7];
    const float* ln_f_b = (const float*)d_in[8];
    const float* gamma  = (const float*)d_in[9];
    const float* Wv   = (const float*)d_in[10];
    const float* bv   = (const float*)d_in[11];
    const float* Wo   = (const float*)d_in[12];
    const float* bo   = (const float*)d_in[13];
    const float* Wa   = (const float*)d_in[14];
    const float* ba   = (const float*)d_in[15];
    const float* Wout = (const float*)d_in[16];
    const float* bout = (const float*)d_in[17];
    float* out = (float*)d_out;

    __nv_bfloat16 *p_fnorm, *p_sampled, *p_Wv, *p_Wout;
    cudaGetSymbolAddress((void**)&p_fnorm,   g_fnorm);
    cudaGetSymbolAddress((void**)&p_sampled, g_sampled);
    cudaGetSymbolAddress((void**)&p_Wv,      g_Wv_bf);
    cudaGetSymbolAddress((void**)&p_Wout,    g_Wout_bf);

    // 1. LayerNorms (both -> bf16) + weight conversion, fused
    ln_conv_kernel<<<2*NROWS + 288, 128>>>(
        feat, query, ln_f_g, ln_f_b, ln_q_g, ln_q_b, Wv, Wout, Wo, Wa);

    // 2. value = f_norm @ Wv + bv   (bf16 out)
    mma_gemm_kernel<0><<<dim3(CC/BN, NROWS/BM), 256>>>(
        p_fnorm, p_Wv, bv, nullptr, nullptr, nullptr);

    // 3. sampling params (tensor-core GEMM + softmax + coords)
    params_mma_kernel<<<NROWS/PBM, 128>>>(bo, ba, refp);

    // 4. bilinear sampling (bf16 HFMA2, 4 queries/block)
    sample_kernel<<<NROWS/4, 384>>>();

    // 5. out = query + gamma * (sampled @ Wout + bout)
    mma_gemm_kernel<1><<<dim3(CC/BN, NROWS/BM), 256>>>(
        p_sampled, p_Wout, bout, query, gamma, out);
}